// round 2
// baseline (speedup 1.0000x reference)
#include <cuda_runtime.h>
#include <math.h>

#define TOK 1024
#define NE 8
#define HD 1024
#define ID 768
#define NPAIR (2*TOK)
#define KB13 (HD/128)   // 8 scale blocks along H
#define KB2  (ID/128)   // 6 scale blocks along I

// ---- scratch (static device globals: no allocation at launch time) ----
__device__ int   g_cnt[NE];
__device__ int   g_bucket[NE][TOK];
__device__ float g_wt[NPAIR];
__device__ float g_act[(size_t)NPAIR * ID];   // activations per pair (6.3 MB)
__device__ float g_os [(size_t)NPAIR * HD];   // per-slot outputs      (8.4 MB)

// ---------------------------------------------------------------------
// Routing: softmax top-2 per token, bucket pairs by expert.
// One block, TOK threads. Deterministic final output (bucket order only
// affects which block computes a row, not its value).
// ---------------------------------------------------------------------
__global__ void routing_kernel(const float* __restrict__ rl) {
    int t = threadIdx.x;
    if (t < NE) g_cnt[t] = 0;
    __syncthreads();

    float l[NE];
#pragma unroll
    for (int e = 0; e < NE; e++) l[e] = rl[t * NE + e];

    // top-1 (lowest index wins ties, matching jax top_k)
    int i0 = 0; float v0 = l[0];
#pragma unroll
    for (int e = 1; e < NE; e++) if (l[e] > v0) { v0 = l[e]; i0 = e; }
    // top-2
    int i1 = -1; float v1 = -3.4e38f;
#pragma unroll
    for (int e = 0; e < NE; e++) if (e != i0 && l[e] > v1) { v1 = l[e]; i1 = e; }

    // renormalized pair weights (softmax denominator cancels)
    float e0 = expf(v0 - v0), e1 = expf(v1 - v0);   // e0 = 1
    float inv = 1.0f / (e0 + e1);
    int p0 = 2 * t, p1 = 2 * t + 1;
    g_wt[p0] = e0 * inv;
    g_wt[p1] = e1 * inv;

    int pos0 = atomicAdd(&g_cnt[i0], 1); g_bucket[i0][pos0] = p0;
    int pos1 = atomicAdd(&g_cnt[i1], 1); g_bucket[i1][pos1] = p1;
}

// ---------------------------------------------------------------------
// GEMM1: for expert e, rows = bucketed pairs, cols = intermediate dim.
// Computes gate AND up columns in the same block; epilogue = silu(g)*u.
// A = x[token] (M x 1024), B = dequant(w13[e])  (2I x 1024, row-major K).
// Tile 64x64x16, 256 threads, 4x4 microtile (x2 accumulator sets).
// ---------------------------------------------------------------------
__global__ __launch_bounds__(256) void gemm1_kernel(
    const float* __restrict__ x,
    const float* __restrict__ w13,
    const float* __restrict__ w13s)
{
    int e  = blockIdx.z;
    int Me = g_cnt[e];
    int m0 = blockIdx.y * 64;
    if (m0 >= Me) return;
    int n0 = blockIdx.x * 64;

    __shared__ float As[16][68];
    __shared__ float Bg[16][68];
    __shared__ float Bu[16][68];

    int tid = threadIdx.x;
    int lr  = tid >> 2;          // 0..63 : row handled by this thread for loads
    int lk  = (tid & 3) * 4;     // k offset (float4)

    int arow = m0 + lr;
    int tokr = (arow < Me) ? (g_bucket[e][arow] >> 1) : 0;
    const float* aptr = x + (size_t)tokr * HD;

    int gr = n0 + lr;
    const float* gptr  = w13  + ((size_t)e * 2 * ID + gr) * HD;
    const float* uptr  = w13  + ((size_t)e * 2 * ID + ID + gr) * HD;
    const float* gsptr = w13s + ((size_t)e * 2 * ID + gr) * KB13;
    const float* usptr = w13s + ((size_t)e * 2 * ID + ID + gr) * KB13;

    float accg[4][4] = {}, accu[4][4] = {};
    int cx = (tid & 15) * 4;
    int cy = (tid >> 4) * 4;

    for (int k0 = 0; k0 < HD; k0 += 16) {
        int kb = k0 >> 7;
        float4 av = *(const float4*)(aptr + k0 + lk);
        float  sg = gsptr[kb];
        float  su = usptr[kb];
        float4 gv = *(const float4*)(gptr + k0 + lk);
        float4 uv = *(const float4*)(uptr + k0 + lk);

        __syncthreads();
        As[lk + 0][lr] = av.x; As[lk + 1][lr] = av.y;
        As[lk + 2][lr] = av.z; As[lk + 3][lr] = av.w;
        Bg[lk + 0][lr] = gv.x * sg; Bg[lk + 1][lr] = gv.y * sg;
        Bg[lk + 2][lr] = gv.z * sg; Bg[lk + 3][lr] = gv.w * sg;
        Bu[lk + 0][lr] = uv.x * su; Bu[lk + 1][lr] = uv.y * su;
        Bu[lk + 2][lr] = uv.z * su; Bu[lk + 3][lr] = uv.w * su;
        __syncthreads();

#pragma unroll
        for (int k = 0; k < 16; k++) {
            float4 a  = *(const float4*)&As[k][cy];
            float4 bg = *(const float4*)&Bg[k][cx];
            float4 bu = *(const float4*)&Bu[k][cx];
            float am[4] = {a.x, a.y, a.z, a.w};
            float bgm[4] = {bg.x, bg.y, bg.z, bg.w};
            float bum[4] = {bu.x, bu.y, bu.z, bu.w};
#pragma unroll
            for (int i = 0; i < 4; i++)
#pragma unroll
                for (int j = 0; j < 4; j++) {
                    accg[i][j] = fmaf(am[i], bgm[j], accg[i][j]);
                    accu[i][j] = fmaf(am[i], bum[j], accu[i][j]);
                }
        }
    }

#pragma unroll
    for (int i = 0; i < 4; i++) {
        int r = m0 + cy + i;
        if (r < Me) {
            int p = g_bucket[e][r];
            float* dst = g_act + (size_t)p * ID + n0 + cx;
#pragma unroll
            for (int j = 0; j < 4; j++) {
                float g = accg[i][j], u = accu[i][j];
                float s = g / (1.0f + expf(-g));
                dst[j] = s * u;
            }
        }
    }
}

// ---------------------------------------------------------------------
// GEMM2: out_slot[p, h] = wt[p] * sum_i act[p,i] * dequant(w2[e])[h,i]
// Tile 64x64x16, 256 threads, 4x4 microtile.
// ---------------------------------------------------------------------
__global__ __launch_bounds__(256) void gemm2_kernel(
    const float* __restrict__ w2,
    const float* __restrict__ w2s)
{
    int e  = blockIdx.z;
    int Me = g_cnt[e];
    int m0 = blockIdx.y * 64;
    if (m0 >= Me) return;
    int n0 = blockIdx.x * 64;   // h tile

    __shared__ float As[16][68];
    __shared__ float Bs[16][68];

    int tid = threadIdx.x;
    int lr  = tid >> 2;
    int lk  = (tid & 3) * 4;

    int arow = m0 + lr;
    int pr   = (arow < Me) ? g_bucket[e][arow] : 0;
    const float* aptr = g_act + (size_t)pr * ID;

    int hr = n0 + lr;
    const float* bptr = w2  + ((size_t)e * HD + hr) * ID;
    const float* sptr = w2s + ((size_t)e * HD + hr) * KB2;

    float acc[4][4] = {};
    int cx = (tid & 15) * 4;
    int cy = (tid >> 4) * 4;

    for (int k0 = 0; k0 < ID; k0 += 16) {
        int kb = k0 >> 7;
        float4 av = *(const float4*)(aptr + k0 + lk);
        float  sb = sptr[kb];
        float4 bv = *(const float4*)(bptr + k0 + lk);

        __syncthreads();
        As[lk + 0][lr] = av.x; As[lk + 1][lr] = av.y;
        As[lk + 2][lr] = av.z; As[lk + 3][lr] = av.w;
        Bs[lk + 0][lr] = bv.x * sb; Bs[lk + 1][lr] = bv.y * sb;
        Bs[lk + 2][lr] = bv.z * sb; Bs[lk + 3][lr] = bv.w * sb;
        __syncthreads();

#pragma unroll
        for (int k = 0; k < 16; k++) {
            float4 a = *(const float4*)&As[k][cy];
            float4 b = *(const float4*)&Bs[k][cx];
            float am[4] = {a.x, a.y, a.z, a.w};
            float bm[4] = {b.x, b.y, b.z, b.w};
#pragma unroll
            for (int i = 0; i < 4; i++)
#pragma unroll
                for (int j = 0; j < 4; j++)
                    acc[i][j] = fmaf(am[i], bm[j], acc[i][j]);
        }
    }

#pragma unroll
    for (int i = 0; i < 4; i++) {
        int r = m0 + cy + i;
        if (r < Me) {
            int p  = g_bucket[e][r];
            float w = g_wt[p];
            float* dst = g_os + (size_t)p * HD + n0 + cx;
#pragma unroll
            for (int j = 0; j < 4; j++)
                dst[j] = w * acc[i][j];
        }
    }
}

// ---------------------------------------------------------------------
// Combine: out[t,h] = os[2t,h] + os[2t+1,h]
// ---------------------------------------------------------------------
__global__ void combine_kernel(float* __restrict__ out) {
    int idx = blockIdx.x * 256 + threadIdx.x;     // 0 .. TOK*HD-1
    int t = idx >> 10;                            // HD = 1024
    int h = idx & (HD - 1);
    out[idx] = g_os[(size_t)(2 * t) * HD + h] + g_os[(size_t)(2 * t + 1) * HD + h];
}

// ---------------------------------------------------------------------
extern "C" void kernel_launch(void* const* d_in, const int* in_sizes, int n_in,
                              void* d_out, int out_size) {
    const float* x    = (const float*)d_in[0];
    const float* rl   = (const float*)d_in[1];
    const float* w13  = (const float*)d_in[2];
    const float* w13s = (const float*)d_in[3];
    const float* w2   = (const float*)d_in[4];
    const float* w2s  = (const float*)d_in[5];
    float* out = (float*)d_out;

    routing_kernel<<<1, TOK>>>(rl);

    dim3 g1(ID / 64, TOK / 64, NE);   // 12 x 16 x 8
    gemm1_kernel<<<g1, 256>>>(x, w13, w13s);

    dim3 g2(HD / 64, TOK / 64, NE);   // 16 x 16 x 8
    gemm2_kernel<<<g2, 256>>>(w2, w2s);

    combine_kernel<<<(TOK * HD) / 256, 256>>>(out);
}

// round 8
// speedup vs baseline: 1.2646x; 1.2646x over previous
#include <cuda_runtime.h>
#include <cuda_bf16.h>
#include <cstdint>
#include <math.h>

#define TOK 1024
#define NE 8
#define HD 1024
#define ID 768
#define NPAIR (2*TOK)

// ------------------------- device scratch (static, no allocs) -------------
__device__ int   g_cnt[NE];
__device__ int   g_bucket[NE][TOK];
__device__ float g_wt[NPAIR];

__device__ __nv_bfloat16 xs_h[(size_t)TOK*HD];
__device__ __nv_bfloat16 xs_l[(size_t)TOK*HD];
__device__ __nv_bfloat16 w13h[(size_t)NE*2*ID*HD];
__device__ __nv_bfloat16 w13l[(size_t)NE*2*ID*HD];
__device__ __nv_bfloat16 w2h[(size_t)NE*HD*ID];
__device__ __nv_bfloat16 w2l[(size_t)NE*HD*ID];
__device__ __nv_bfloat16 act_h[(size_t)NPAIR*ID];
__device__ __nv_bfloat16 act_l[(size_t)NPAIR*ID];
__device__ float g_os[(size_t)NPAIR*HD];

// ------------------------- PTX helpers (baseline ISA only) ----------------
__device__ __forceinline__ uint32_t smem_u32(const void* p) {
    uint32_t a;
    asm("{ .reg .u64 t; cvta.to.shared.u64 t, %1; cvt.u32.u64 %0, t; }" : "=r"(a) : "l"(p));
    return a;
}
__device__ __forceinline__ void cp16(uint32_t dst, const void* src) {
    asm volatile("cp.async.cg.shared.global [%0], [%1], 16;" :: "r"(dst), "l"(src));
}
__device__ __forceinline__ void cp_commit() {
    asm volatile("cp.async.commit_group;");
}
__device__ __forceinline__ void ldsm4(uint32_t* r, uint32_t addr) {
    asm volatile("ldmatrix.sync.aligned.m8n8.x4.shared.b16 {%0,%1,%2,%3}, [%4];"
        : "=r"(r[0]), "=r"(r[1]), "=r"(r[2]), "=r"(r[3]) : "r"(addr));
}
__device__ __forceinline__ void mma_bf16(float* d, const uint32_t* a, uint32_t b0, uint32_t b1) {
    asm volatile("mma.sync.aligned.m16n8k16.row.col.f32.bf16.bf16.f32 "
        "{%0,%1,%2,%3}, {%4,%5,%6,%7}, {%8,%9}, {%0,%1,%2,%3};"
        : "+f"(d[0]), "+f"(d[1]), "+f"(d[2]), "+f"(d[3])
        : "r"(a[0]), "r"(a[1]), "r"(a[2]), "r"(a[3]), "r"(b0), "r"(b1));
}

// split two fp32 into packed bf16x2 hi (truncated top bits) + bf16x2 lo (residual)
__device__ __forceinline__ void split2(float a, float b, uint32_t& hi, uint32_t& lo) {
    uint32_t ai = __float_as_uint(a), bi = __float_as_uint(b);
    hi = __byte_perm(ai, bi, 0x7632);            // low half = a.top16, high = b.top16
    float ah = __uint_as_float(ai & 0xffff0000u);
    float bh = __uint_as_float(bi & 0xffff0000u);
    float al = a - ah, bl = b - bh;
    asm("cvt.rn.bf16x2.f32 %0, %1, %2;" : "=r"(lo) : "f"(bl), "f"(al));
}

// ------------------------- routing ---------------------------------------
__global__ void routing_kernel(const float* __restrict__ rl) {
    int t = threadIdx.x;
    if (t < NE) g_cnt[t] = 0;
    __syncthreads();
    float l[NE];
#pragma unroll
    for (int e = 0; e < NE; e++) l[e] = rl[t * NE + e];
    int i0 = 0; float v0 = l[0];
#pragma unroll
    for (int e = 1; e < NE; e++) if (l[e] > v0) { v0 = l[e]; i0 = e; }
    int i1 = -1; float v1 = -3.4e38f;
#pragma unroll
    for (int e = 0; e < NE; e++) if (e != i0 && l[e] > v1) { v1 = l[e]; i1 = e; }
    float e1 = expf(v1 - v0);
    float inv = 1.0f / (1.0f + e1);
    int p0 = 2 * t, p1 = 2 * t + 1;
    g_wt[p0] = inv;
    g_wt[p1] = e1 * inv;
    int pos0 = atomicAdd(&g_cnt[i0], 1); g_bucket[i0][pos0] = p0;
    int pos1 = atomicAdd(&g_cnt[i1], 1); g_bucket[i1][pos1] = p1;
}

// ------------------------- pre-pass converts ------------------------------
__global__ void convert_x_kernel(const float* __restrict__ x) {
    size_t i8 = ((size_t)blockIdx.x * 256 + threadIdx.x) * 8;
    float4 v0 = *(const float4*)(x + i8), v1 = *(const float4*)(x + i8 + 4);
    uint32_t H[4], L[4];
    split2(v0.x, v0.y, H[0], L[0]); split2(v0.z, v0.w, H[1], L[1]);
    split2(v1.x, v1.y, H[2], L[2]); split2(v1.z, v1.w, H[3], L[3]);
    *(uint4*)(xs_h + i8) = make_uint4(H[0], H[1], H[2], H[3]);
    *(uint4*)(xs_l + i8) = make_uint4(L[0], L[1], L[2], L[3]);
}

__global__ void convert_w13_kernel(const float* __restrict__ w, const float* __restrict__ ws) {
    size_t i8 = ((size_t)blockIdx.x * 256 + threadIdx.x) * 8;
    size_t row = i8 >> 10;
    int h0 = (int)(i8 & 1023);
    float s = ws[row * (HD / 128) + (h0 >> 7)];
    float4 v0 = *(const float4*)(w + i8), v1 = *(const float4*)(w + i8 + 4);
    uint32_t H[4], L[4];
    split2(v0.x * s, v0.y * s, H[0], L[0]); split2(v0.z * s, v0.w * s, H[1], L[1]);
    split2(v1.x * s, v1.y * s, H[2], L[2]); split2(v1.z * s, v1.w * s, H[3], L[3]);
    *(uint4*)(w13h + i8) = make_uint4(H[0], H[1], H[2], H[3]);
    *(uint4*)(w13l + i8) = make_uint4(L[0], L[1], L[2], L[3]);
}

__global__ void convert_w2_kernel(const float* __restrict__ w, const float* __restrict__ ws) {
    size_t i8 = ((size_t)blockIdx.x * 256 + threadIdx.x) * 8;
    size_t row = i8 / ID;
    int c0 = (int)(i8 - row * ID);
    float s = ws[row * (ID / 128) + (c0 >> 7)];
    float4 v0 = *(const float4*)(w + i8), v1 = *(const float4*)(w + i8 + 4);
    uint32_t H[4], L[4];
    split2(v0.x * s, v0.y * s, H[0], L[0]); split2(v0.z * s, v0.w * s, H[1], L[1]);
    split2(v1.x * s, v1.y * s, H[2], L[2]); split2(v1.z * s, v1.w * s, H[3], L[3]);
    *(uint4*)(w2h + i8) = make_uint4(H[0], H[1], H[2], H[3]);
    *(uint4*)(w2l + i8) = make_uint4(L[0], L[1], L[2], L[3]);
}

// ===========================================================================
// Shared GEMM geometry:
//   block tile 128(m) x 128(n), K-chunk 64, smem per stage:
//     [A_hi 16K][A_lo 16K][B_hi 16K][B_lo 16K] = 64KB, 2 stages = 128KB.
//   rows stored as 128B (64 bf16) with SW128 swizzle: off = r*128 + (kb ^ ((r&7)<<4))
//   8 warps: mw = wid>>2 (2 m-rows of 64), nw = wid&3 (4 n-cols of 32)
// ===========================================================================
#define STAGE 65536
#define OPTILE 16384

// ------------------------- GEMM1 (x @ w13^T, fused silu*up) ---------------
__global__ __launch_bounds__(256, 1) void gemm1_kernel() {
    int e  = blockIdx.z;
    int Me = g_cnt[e];
    int m0 = blockIdx.y * 128;
    if (m0 >= Me) return;
    int n0g = blockIdx.x * 64;

    extern __shared__ __align__(16) char dynraw[];
    __shared__ int s_tok[128];
    __shared__ int s_pair[128];

    int tid = threadIdx.x, wid = tid >> 5, lane = tid & 31;
    uint32_t dynb0 = smem_u32(dynraw);
    uint32_t dynb = (dynb0 + 1023u) & ~1023u;
    float* s_up = (float*)(dynraw + (dynb - dynb0));   // reused after mainloop

    if (tid < 128) {
        int r = m0 + tid;
        int pr = (r < Me) ? g_bucket[e][r] : 0;
        s_pair[tid] = (r < Me) ? pr : -1;
        s_tok[tid]  = pr >> 1;
    }
    __syncthreads();

    // per-thread cp.async task map: 16 tasks x 16B
    const __nv_bfloat16* gbase[16];
    uint32_t sdst[16];
#pragma unroll
    for (int it = 0; it < 16; it++) {
        int task = (tid >> 3) + it * 32;
        int tile = task >> 7, row = task & 127, piece = tid & 7;
        const __nv_bfloat16* p;
        if (tile == 0)      p = xs_h + (size_t)s_tok[row] * HD;
        else if (tile == 1) p = xs_l + (size_t)s_tok[row] * HD;
        else {
            int brow = (row < 64) ? (n0g + row) : (ID + n0g + (row - 64));
            p = ((tile == 2) ? w13h : w13l) + ((size_t)e * (2 * ID) + brow) * (size_t)HD;
        }
        gbase[it] = p + piece * 8;
        sdst[it] = dynb + tile * OPTILE + row * 128 + ((piece * 16) ^ ((row & 7) << 4));
    }

    // prologue: chunk 0 -> stage 0
#pragma unroll
    for (int it = 0; it < 16; it++) cp16(sdst[it], gbase[it]);
    cp_commit();

    float acc[4][4][4] = {};
    int mw = wid >> 2, nw = wid & 3;
    const int NC = HD / 64;   // 16

    for (int c = 0; c < NC; c++) {
        int st = c & 1;
        if (c + 1 < NC) {
            uint32_t so = ((c + 1) & 1) * STAGE;
            const __nv_bfloat16* goff = (const __nv_bfloat16*)0 + (size_t)(c + 1) * 64;
#pragma unroll
            for (int it = 0; it < 16; it++) cp16(sdst[it] + so, gbase[it] + (size_t)(c + 1) * 64);
            (void)goff;
            cp_commit();
            asm volatile("cp.async.wait_group 1;");
        } else {
            asm volatile("cp.async.wait_group 0;");
        }
        __syncthreads();

        uint32_t base = dynb + st * STAGE;
#pragma unroll
        for (int kt = 0; kt < 4; kt++) {
            int kel = kt * 16 + (lane >> 4) * 8;
            uint32_t ah[4][4], al[4][4], bh[2][4], bl[2][4];
#pragma unroll
            for (int mt = 0; mt < 4; mt++) {
                int row = mw * 64 + mt * 16 + (lane & 15);
                uint32_t ad = base + row * 128 + ((kel * 2) ^ ((row & 7) << 4));
                ldsm4(ah[mt], ad);
                ldsm4(al[mt], ad + OPTILE);
            }
#pragma unroll
            for (int nb = 0; nb < 2; nb++) {
                int row = nw * 32 + nb * 16 + (lane & 15);
                uint32_t bd = base + 2 * OPTILE + row * 128 + ((kel * 2) ^ ((row & 7) << 4));
                ldsm4(bh[nb], bd);
                ldsm4(bl[nb], bd + OPTILE);
            }
#pragma unroll
            for (int mt = 0; mt < 4; mt++)
#pragma unroll
                for (int nt = 0; nt < 4; nt++) {
                    uint32_t h0 = bh[nt >> 1][nt & 1], h1 = bh[nt >> 1][(nt & 1) + 2];
                    uint32_t l0 = bl[nt >> 1][nt & 1], l1 = bl[nt >> 1][(nt & 1) + 2];
                    mma_bf16(acc[mt][nt], ah[mt], h0, h1);
                    mma_bf16(acc[mt][nt], ah[mt], l0, l1);
                    mma_bf16(acc[mt][nt], al[mt], h0, h1);
                }
        }
        __syncthreads();
    }

    // ---- epilogue: up warps (nw>=2) stash to smem, gate warps fuse silu ----
    int g = lane >> 2, t2 = (lane & 3) * 2;
    if (nw >= 2) {
#pragma unroll
        for (int mt = 0; mt < 4; mt++)
#pragma unroll
            for (int nt = 0; nt < 4; nt++) {
                int j = (nw - 2) * 32 + nt * 8 + t2;
                int r = mw * 64 + mt * 16 + g;
                *(float2*)&s_up[r * 66 + j]       = make_float2(acc[mt][nt][0], acc[mt][nt][1]);
                *(float2*)&s_up[(r + 8) * 66 + j] = make_float2(acc[mt][nt][2], acc[mt][nt][3]);
            }
    }
    __syncthreads();
    if (nw < 2) {
#pragma unroll
        for (int mt = 0; mt < 4; mt++)
#pragma unroll
            for (int nt = 0; nt < 4; nt++) {
                int j = nw * 32 + nt * 8 + t2;
                int r0 = mw * 64 + mt * 16 + g, r1 = r0 + 8;
                float2 u0 = *(float2*)&s_up[r0 * 66 + j];
                float2 u1 = *(float2*)&s_up[r1 * 66 + j];
                float g00 = acc[mt][nt][0], g01 = acc[mt][nt][1];
                float g10 = acc[mt][nt][2], g11 = acc[mt][nt][3];
                float a00 = u0.x * (g00 / (1.0f + __expf(-g00)));
                float a01 = u0.y * (g01 / (1.0f + __expf(-g01)));
                float a10 = u1.x * (g10 / (1.0f + __expf(-g10)));
                float a11 = u1.y * (g11 / (1.0f + __expf(-g11)));
                uint32_t hi, lo;
                int p0 = s_pair[r0], p1 = s_pair[r1];
                if (p0 >= 0) {
                    split2(a00, a01, hi, lo);
                    *(uint32_t*)(act_h + (size_t)p0 * ID + n0g + j) = hi;
                    *(uint32_t*)(act_l + (size_t)p0 * ID + n0g + j) = lo;
                }
                if (p1 >= 0) {
                    split2(a10, a11, hi, lo);
                    *(uint32_t*)(act_h + (size_t)p1 * ID + n0g + j) = hi;
                    *(uint32_t*)(act_l + (size_t)p1 * ID + n0g + j) = lo;
                }
            }
    }
}

// ------------------------- GEMM2 (act @ w2^T, weighted) -------------------
__global__ __launch_bounds__(256, 1) void gemm2_kernel() {
    int e  = blockIdx.z;
    int Me = g_cnt[e];
    int m0 = blockIdx.y * 128;
    if (m0 >= Me) return;
    int n0 = blockIdx.x * 128;

    extern __shared__ __align__(16) char dynraw[];
    __shared__ int s_arow[128];
    __shared__ int s_pair[128];

    int tid = threadIdx.x, wid = tid >> 5, lane = tid & 31;
    uint32_t dynb0 = smem_u32(dynraw);
    uint32_t dynb = (dynb0 + 1023u) & ~1023u;

    if (tid < 128) {
        int r = m0 + tid;
        int pr = (r < Me) ? g_bucket[e][r] : 0;
        s_pair[tid] = (r < Me) ? pr : -1;
        s_arow[tid] = pr;
    }
    __syncthreads();

    const __nv_bfloat16* gbase[16];
    uint32_t sdst[16];
#pragma unroll
    for (int it = 0; it < 16; it++) {
        int task = (tid >> 3) + it * 32;
        int tile = task >> 7, row = task & 127, piece = tid & 7;
        const __nv_bfloat16* p;
        if (tile == 0)      p = act_h + (size_t)s_arow[row] * ID;
        else if (tile == 1) p = act_l + (size_t)s_arow[row] * ID;
        else
            p = ((tile == 2) ? w2h : w2l) + ((size_t)e * HD + (n0 + row)) * (size_t)ID;
        gbase[it] = p + piece * 8;
        sdst[it] = dynb + tile * OPTILE + row * 128 + ((piece * 16) ^ ((row & 7) << 4));
    }

#pragma unroll
    for (int it = 0; it < 16; it++) cp16(sdst[it], gbase[it]);
    cp_commit();

    float acc[4][4][4] = {};
    int mw = wid >> 2, nw = wid & 3;
    const int NC = ID / 64;   // 12

    for (int c = 0; c < NC; c++) {
        int st = c & 1;
        if (c + 1 < NC) {
            uint32_t so = ((c + 1) & 1) * STAGE;
#pragma unroll
            for (int it = 0; it < 16; it++) cp16(sdst[it] + so, gbase[it] + (size_t)(c + 1) * 64);
            cp_commit();
            asm volatile("cp.async.wait_group 1;");
        } else {
            asm volatile("cp.async.wait_group 0;");
        }
        __syncthreads();

        uint32_t base = dynb + st * STAGE;
#pragma unroll
        for (int kt = 0; kt < 4; kt++) {
            int kel = kt * 16 + (lane >> 4) * 8;
            uint32_t ah[4][4], al[4][4], bh[2][4], bl[2][4];
#pragma unroll
            for (int mt = 0; mt < 4; mt++) {
                int row = mw * 64 + mt * 16 + (lane & 15);
                uint32_t ad = base + row * 128 + ((kel * 2) ^ ((row & 7) << 4));
                ldsm4(ah[mt], ad);
                ldsm4(al[mt], ad + OPTILE);
            }
#pragma unroll
            for (int nb = 0; nb < 2; nb++) {
                int row = nw * 32 + nb * 16 + (lane & 15);
                uint32_t bd = base + 2 * OPTILE + row * 128 + ((kel * 2) ^ ((row & 7) << 4));
                ldsm4(bh[nb], bd);
                ldsm4(bl[nb], bd + OPTILE);
            }
#pragma unroll
            for (int mt = 0; mt < 4; mt++)
#pragma unroll
                for (int nt = 0; nt < 4; nt++) {
                    uint32_t h0 = bh[nt >> 1][nt & 1], h1 = bh[nt >> 1][(nt & 1) + 2];
                    uint32_t l0 = bl[nt >> 1][nt & 1], l1 = bl[nt >> 1][(nt & 1) + 2];
                    mma_bf16(acc[mt][nt], ah[mt], h0, h1);
                    mma_bf16(acc[mt][nt], ah[mt], l0, l1);
                    mma_bf16(acc[mt][nt], al[mt], h0, h1);
                }
        }
        __syncthreads();
    }

    // ---- epilogue: weighted store to per-slot planes ----
    int g = lane >> 2, t2 = (lane & 3) * 2;
#pragma unroll
    for (int mt = 0; mt < 4; mt++)
#pragma unroll
        for (int nt = 0; nt < 4; nt++) {
            int j = n0 + nw * 32 + nt * 8 + t2;
            int r0 = mw * 64 + mt * 16 + g, r1 = r0 + 8;
            int p0 = s_pair[r0], p1 = s_pair[r1];
            if (p0 >= 0) {
                float wf = g_wt[p0];
                *(float2*)(g_os + (size_t)p0 * HD + j) =
                    make_float2(wf * acc[mt][nt][0], wf * acc[mt][nt][1]);
            }
            if (p1 >= 0) {
                float wf = g_wt[p1];
                *(float2*)(g_os + (size_t)p1 * HD + j) =
                    make_float2(wf * acc[mt][nt][2], wf * acc[mt][nt][3]);
            }
        }
}

// ------------------------- combine ----------------------------------------
__global__ void combine_kernel(float4* __restrict__ out) {
    int i = blockIdx.x * 256 + threadIdx.x;          // over TOK*HD/4
    int t = i >> 8;                                  // 256 float4 per row
    int h4 = i & 255;
    const float4* a = reinterpret_cast<const float4*>(g_os);
    float4 x = a[(size_t)(2 * t) * 256 + h4];
    float4 y = a[(size_t)(2 * t + 1) * 256 + h4];
    out[i] = make_float4(x.x + y.x, x.y + y.y, x.z + y.z, x.w + y.w);
}

// ------------------------- launch -----------------------------------------
extern "C" void kernel_launch(void* const* d_in, const int* in_sizes, int n_in,
                              void* d_out, int out_size) {
    const float* x    = (const float*)d_in[0];
    const float* rl   = (const float*)d_in[1];
    const float* w13  = (const float*)d_in[2];
    const float* w13s = (const float*)d_in[3];
    const float* w2   = (const float*)d_in[4];
    const float* w2s  = (const float*)d_in[5];
    float* out = (float*)d_out;

    const int DSM = 2 * STAGE + 1024;   // 132 KB
    cudaFuncSetAttribute(gemm1_kernel, cudaFuncAttributeMaxDynamicSharedMemorySize, DSM);
    cudaFuncSetAttribute(gemm2_kernel, cudaFuncAttributeMaxDynamicSharedMemorySize, DSM);

    routing_kernel<<<1, TOK>>>(rl);
    convert_x_kernel<<<(TOK * HD) / (256 * 8), 256>>>(x);
    convert_w13_kernel<<<(NE * 2 * ID * HD) / (256 * 8), 256>>>(w13, w13s);
    convert_w2_kernel<<<(NE * HD * ID) / (256 * 8), 256>>>(w2, w2s);

    dim3 g1(ID / 64, 8, NE);    // 12 x 8 x 8 (m-tiles beyond Me early-exit)
    gemm1_kernel<<<g1, 256, DSM>>>();

    dim3 g2(HD / 128, 8, NE);   // 8 x 8 x 8
    gemm2_kernel<<<g2, 256, DSM>>>();

    combine_kernel<<<(TOK * HD) / (4 * 256), 256>>>(reinterpret_cast<float4*>(out));
}

// round 9
// speedup vs baseline: 2.7048x; 2.1388x over previous
#include <cuda_runtime.h>
#include <cuda_bf16.h>
#include <cstdint>
#include <math.h>

#define TOK 1024
#define NE 8
#define HD 1024
#define ID 768
#define NPAIR (2*TOK)

#define STAGE 65536          // per-stage smem: A 32KB + B 32KB
#define OPB   32768          // B offset within stage

// ------------------------- device scratch (static, no allocs) -------------
__device__ int   g_cnt[NE];
__device__ int   g_bucket[NE][TOK];
__device__ float g_wt[NPAIR];

__device__ float xs[(size_t)TOK*HD];          // tf32-rounded x
__device__ float g_act[(size_t)NPAIR*ID];     // tf32-rounded activations
__device__ float g_os[(size_t)NPAIR*HD];      // per-slot outputs

// ------------------------- PTX helpers (baseline ISA only) ----------------
__device__ __forceinline__ uint32_t smem_u32(const void* p) {
    uint32_t a;
    asm("{ .reg .u64 t; cvta.to.shared.u64 t, %1; cvt.u32.u64 %0, t; }" : "=r"(a) : "l"(p));
    return a;
}
__device__ __forceinline__ void cp16(uint32_t dst, const void* src) {
    asm volatile("cp.async.cg.shared.global [%0], [%1], 16;" :: "r"(dst), "l"(src));
}
__device__ __forceinline__ void cp_commit() {
    asm volatile("cp.async.commit_group;");
}
__device__ __forceinline__ void ldsm4(uint32_t* r, uint32_t addr) {
    asm volatile("ldmatrix.sync.aligned.m8n8.x4.shared.b16 {%0,%1,%2,%3}, [%4];"
        : "=r"(r[0]), "=r"(r[1]), "=r"(r[2]), "=r"(r[3]) : "r"(addr));
}
__device__ __forceinline__ void mma_tf32(float* d, const uint32_t* a, uint32_t b0, uint32_t b1) {
    asm volatile("mma.sync.aligned.m16n8k8.row.col.f32.tf32.tf32.f32 "
        "{%0,%1,%2,%3}, {%4,%5,%6,%7}, {%8,%9}, {%0,%1,%2,%3};"
        : "+f"(d[0]), "+f"(d[1]), "+f"(d[2]), "+f"(d[3])
        : "r"(a[0]), "r"(a[1]), "r"(a[2]), "r"(a[3]), "r"(b0), "r"(b1));
}
__device__ __forceinline__ uint32_t to_tf32(float f) {
    uint32_t r;
    asm("cvt.rna.tf32.f32 %0, %1;" : "=r"(r) : "f"(f));
    return r;
}
__device__ __forceinline__ void sts128(uint32_t addr, uint4 v) {
    asm volatile("st.shared.v4.b32 [%0], {%1,%2,%3,%4};"
                 :: "r"(addr), "r"(v.x), "r"(v.y), "r"(v.z), "r"(v.w));
}

// ------------------------- routing ---------------------------------------
__global__ void routing_kernel(const float* __restrict__ rl) {
    int t = threadIdx.x;
    if (t < NE) g_cnt[t] = 0;
    __syncthreads();
    float l[NE];
#pragma unroll
    for (int e = 0; e < NE; e++) l[e] = rl[t * NE + e];
    int i0 = 0; float v0 = l[0];
#pragma unroll
    for (int e = 1; e < NE; e++) if (l[e] > v0) { v0 = l[e]; i0 = e; }
    int i1 = -1; float v1 = -3.4e38f;
#pragma unroll
    for (int e = 0; e < NE; e++) if (e != i0 && l[e] > v1) { v1 = l[e]; i1 = e; }
    float e1 = expf(v1 - v0);
    float inv = 1.0f / (1.0f + e1);
    int p0 = 2 * t, p1 = 2 * t + 1;
    g_wt[p0] = inv;
    g_wt[p1] = e1 * inv;
    int pos0 = atomicAdd(&g_cnt[i0], 1); g_bucket[i0][pos0] = p0;
    int pos1 = atomicAdd(&g_cnt[i1], 1); g_bucket[i1][pos1] = p1;
}

// ------------------------- x prepass: tf32 rounding -----------------------
__global__ void convert_x_kernel(const float* __restrict__ x) {
    size_t i4 = ((size_t)blockIdx.x * 256 + threadIdx.x) * 4;
    float4 v = *(const float4*)(x + i4);
    float4 o;
    o.x = __uint_as_float(to_tf32(v.x));
    o.y = __uint_as_float(to_tf32(v.y));
    o.z = __uint_as_float(to_tf32(v.z));
    o.w = __uint_as_float(to_tf32(v.w));
    *(float4*)(xs + i4) = o;
}

// ===========================================================================
// GEMM geometry: block tile 128(m) x 128(n), K-chunk 64 fp32.
// smem row = 64 fp32 = 256B, swizzle: off = r*256 + (kb ^ ((r&7)<<4)).
// A (tokens/act) via cp.async; B (weights) register-staged with fused
// dequant (scale mult) + tf32 rounding. 8 warps: mw=wid>>2, nw=wid&3.
// tf32 m16n8k8 fragments load via ldmatrix.b16 (b32 elem == one lane pair).
// ===========================================================================

// ------------------------- GEMM1 (x @ w13^T, fused silu*up) ---------------
__global__ __launch_bounds__(256, 1) void gemm1_kernel(
    const float* __restrict__ w13, const float* __restrict__ w13s)
{
    int e  = blockIdx.z;
    int Me = g_cnt[e];
    int m0 = blockIdx.y * 128;
    if (m0 >= Me) return;
    int n0g = blockIdx.x * 64;

    extern __shared__ __align__(16) char dynraw[];
    __shared__ int s_tok[128];
    __shared__ int s_pair[128];

    int tid = threadIdx.x, wid = tid >> 5, lane = tid & 31;
    uint32_t dynb0 = smem_u32(dynraw);
    uint32_t dynb = (dynb0 + 1023u) & ~1023u;
    float* s_up = (float*)(dynraw + (dynb - dynb0));   // reused after mainloop

    if (tid < 128) {
        int r = m0 + tid;
        int pr = (r < Me) ? g_bucket[e][r] : 0;
        s_pair[tid] = (r < Me) ? pr : -1;
        s_tok[tid]  = pr >> 1;
    }
    __syncthreads();

    // per-thread fill maps: 8 tasks, task = tid + it*256 -> row=task>>4, piece=task&15
    uint32_t aoff[8];     // element offset into xs
    uint32_t asts[8];
    uint32_t bwoff[8];    // element offset into w13
    uint32_t bsoff[8];    // element offset into w13s
    uint32_t bsts[8];
#pragma unroll
    for (int it = 0; it < 8; it++) {
        int task = tid + it * 256;
        int row = task >> 4, piece = task & 15;
        aoff[it] = (uint32_t)s_tok[row] * HD + piece * 4;
        asts[it] = dynb + row * 256 + ((piece * 16) ^ ((row & 7) << 4));
        int brow = (row < 64) ? (n0g + row) : (ID + n0g + (row - 64));
        bwoff[it] = (uint32_t)(e * 2 * ID + brow) * HD + piece * 4;
        bsoff[it] = (uint32_t)(e * 2 * ID + brow) * (HD / 128);
        bsts[it] = dynb + OPB + row * 256 + ((piece * 16) ^ ((row & 7) << 4));
    }

    // prologue: B chunk0 -> regs, A chunk0 -> cp.async
    uint4 breg[8]; float bs[8];
#pragma unroll
    for (int it = 0; it < 8; it++) breg[it] = *(const uint4*)(w13 + bwoff[it]);
#pragma unroll
    for (int it = 0; it < 8; it++) bs[it] = w13s[bsoff[it]];
#pragma unroll
    for (int it = 0; it < 8; it++) cp16(asts[it], xs + aoff[it]);
    cp_commit();

    float acc[4][4][4] = {};
    int mw = wid >> 2, nw = wid & 3;

    // ldmatrix lane addressing (constant per thread)
    uint32_t sw   = (lane & 7) << 4;
    uint32_t aOff = (uint32_t)(mw * 64 + ((lane >> 3) & 1) * 8 + (lane & 7)) * 256;
    uint32_t aK   = (lane >> 4) * 16;
    uint32_t bOff = (uint32_t)(nw * 32 + (lane >> 4) * 8 + (lane & 7)) * 256;
    uint32_t bK   = ((lane >> 3) & 1) * 16;

    const int NC = HD / 64;   // 16
    for (int c = 0; c < NC; c++) {
        int st = c & 1;
        uint32_t base = dynb + st * STAGE;
        // store B(c) with fused dequant + tf32 rounding
#pragma unroll
        for (int it = 0; it < 8; it++) {
            float s = bs[it];
            uint4 r = breg[it], w;
            w.x = to_tf32(__uint_as_float(r.x) * s);
            w.y = to_tf32(__uint_as_float(r.y) * s);
            w.z = to_tf32(__uint_as_float(r.z) * s);
            w.w = to_tf32(__uint_as_float(r.w) * s);
            sts128(bsts[it] + st * STAGE, w);
        }
        asm volatile("cp.async.wait_group 0;");
        __syncthreads();
        if (c + 1 < NC) {
            uint32_t ko = (uint32_t)(c + 1) * 64;
#pragma unroll
            for (int it = 0; it < 8; it++) breg[it] = *(const uint4*)(w13 + bwoff[it] + ko);
#pragma unroll
            for (int it = 0; it < 8; it++) bs[it] = w13s[bsoff[it] + ((c + 1) >> 1)];
            uint32_t so = (uint32_t)((c + 1) & 1) * STAGE;
#pragma unroll
            for (int it = 0; it < 8; it++) cp16(asts[it] + so, xs + aoff[it] + ko);
            cp_commit();
        }
        // compute chunk c: 8 k-steps of 8
#pragma unroll
        for (int ks = 0; ks < 8; ks++) {
            uint32_t A[4][4], B[2][4];
#pragma unroll
            for (int mt = 0; mt < 4; mt++)
                ldsm4(A[mt], base + aOff + mt * 4096 + ((aK + ks * 32) ^ sw));
#pragma unroll
            for (int p = 0; p < 2; p++)
                ldsm4(B[p], base + OPB + bOff + p * 4096 + ((bK + ks * 32) ^ sw));
#pragma unroll
            for (int mt = 0; mt < 4; mt++)
#pragma unroll
                for (int nt = 0; nt < 4; nt++)
                    mma_tf32(acc[mt][nt], A[mt], B[nt >> 1][(nt & 1) * 2], B[nt >> 1][(nt & 1) * 2 + 1]);
        }
        __syncthreads();
    }

    // ---- epilogue: up warps (nw>=2) stash to smem, gate warps fuse silu ----
    int g = lane >> 2, t2 = (lane & 3) * 2;
    if (nw >= 2) {
#pragma unroll
        for (int mt = 0; mt < 4; mt++)
#pragma unroll
            for (int nt = 0; nt < 4; nt++) {
                int j = (nw - 2) * 32 + nt * 8 + t2;
                int r = mw * 64 + mt * 16 + g;
                *(float2*)&s_up[r * 66 + j]       = make_float2(acc[mt][nt][0], acc[mt][nt][1]);
                *(float2*)&s_up[(r + 8) * 66 + j] = make_float2(acc[mt][nt][2], acc[mt][nt][3]);
            }
    }
    __syncthreads();
    if (nw < 2) {
#pragma unroll
        for (int mt = 0; mt < 4; mt++)
#pragma unroll
            for (int nt = 0; nt < 4; nt++) {
                int j = nw * 32 + nt * 8 + t2;
                int r0 = mw * 64 + mt * 16 + g, r1 = r0 + 8;
                float2 u0 = *(float2*)&s_up[r0 * 66 + j];
                float2 u1 = *(float2*)&s_up[r1 * 66 + j];
                float g00 = acc[mt][nt][0], g01 = acc[mt][nt][1];
                float g10 = acc[mt][nt][2], g11 = acc[mt][nt][3];
                float a00 = u0.x * (g00 / (1.0f + __expf(-g00)));
                float a01 = u0.y * (g01 / (1.0f + __expf(-g01)));
                float a10 = u1.x * (g10 / (1.0f + __expf(-g10)));
                float a11 = u1.y * (g11 / (1.0f + __expf(-g11)));
                int p0 = s_pair[r0], p1 = s_pair[r1];
                if (p0 >= 0) {
                    *(float2*)(g_act + (size_t)p0 * ID + n0g + j) = make_float2(
                        __uint_as_float(to_tf32(a00)), __uint_as_float(to_tf32(a01)));
                }
                if (p1 >= 0) {
                    *(float2*)(g_act + (size_t)p1 * ID + n0g + j) = make_float2(
                        __uint_as_float(to_tf32(a10)), __uint_as_float(to_tf32(a11)));
                }
            }
    }
}

// ------------------------- GEMM2 (act @ w2^T, weighted) -------------------
__global__ __launch_bounds__(256, 1) void gemm2_kernel(
    const float* __restrict__ w2, const float* __restrict__ w2s)
{
    int e  = blockIdx.z;
    int Me = g_cnt[e];
    int m0 = blockIdx.y * 128;
    if (m0 >= Me) return;
    int n0 = blockIdx.x * 128;

    extern __shared__ __align__(16) char dynraw[];
    __shared__ int s_arow[128];
    __shared__ int s_pair[128];

    int tid = threadIdx.x, wid = tid >> 5, lane = tid & 31;
    uint32_t dynb0 = smem_u32(dynraw);
    uint32_t dynb = (dynb0 + 1023u) & ~1023u;

    if (tid < 128) {
        int r = m0 + tid;
        int pr = (r < Me) ? g_bucket[e][r] : 0;
        s_pair[tid] = (r < Me) ? pr : -1;
        s_arow[tid] = pr;
    }
    __syncthreads();

    uint32_t aoff[8], asts[8], bwoff[8], bsoff[8], bsts[8];
#pragma unroll
    for (int it = 0; it < 8; it++) {
        int task = tid + it * 256;
        int row = task >> 4, piece = task & 15;
        aoff[it] = (uint32_t)s_arow[row] * ID + piece * 4;
        asts[it] = dynb + row * 256 + ((piece * 16) ^ ((row & 7) << 4));
        bwoff[it] = (uint32_t)(e * HD + n0 + row) * ID + piece * 4;
        bsoff[it] = (uint32_t)(e * HD + n0 + row) * (ID / 128);
        bsts[it] = dynb + OPB + row * 256 + ((piece * 16) ^ ((row & 7) << 4));
    }

    uint4 breg[8]; float bs[8];
#pragma unroll
    for (int it = 0; it < 8; it++) breg[it] = *(const uint4*)(w2 + bwoff[it]);
#pragma unroll
    for (int it = 0; it < 8; it++) bs[it] = w2s[bsoff[it]];
#pragma unroll
    for (int it = 0; it < 8; it++) cp16(asts[it], g_act + aoff[it]);
    cp_commit();

    float acc[4][4][4] = {};
    int mw = wid >> 2, nw = wid & 3;

    uint32_t sw   = (lane & 7) << 4;
    uint32_t aOff = (uint32_t)(mw * 64 + ((lane >> 3) & 1) * 8 + (lane & 7)) * 256;
    uint32_t aK   = (lane >> 4) * 16;
    uint32_t bOff = (uint32_t)(nw * 32 + (lane >> 4) * 8 + (lane & 7)) * 256;
    uint32_t bK   = ((lane >> 3) & 1) * 16;

    const int NC = ID / 64;   // 12
    for (int c = 0; c < NC; c++) {
        int st = c & 1;
        uint32_t base = dynb + st * STAGE;
#pragma unroll
        for (int it = 0; it < 8; it++) {
            float s = bs[it];
            uint4 r = breg[it], w;
            w.x = to_tf32(__uint_as_float(r.x) * s);
            w.y = to_tf32(__uint_as_float(r.y) * s);
            w.z = to_tf32(__uint_as_float(r.z) * s);
            w.w = to_tf32(__uint_as_float(r.w) * s);
            sts128(bsts[it] + st * STAGE, w);
        }
        asm volatile("cp.async.wait_group 0;");
        __syncthreads();
        if (c + 1 < NC) {
            uint32_t ko = (uint32_t)(c + 1) * 64;
#pragma unroll
            for (int it = 0; it < 8; it++) breg[it] = *(const uint4*)(w2 + bwoff[it] + ko);
#pragma unroll
            for (int it = 0; it < 8; it++) bs[it] = w2s[bsoff[it] + ((c + 1) >> 1)];
            uint32_t so = (uint32_t)((c + 1) & 1) * STAGE;
#pragma unroll
            for (int it = 0; it < 8; it++) cp16(asts[it] + so, g_act + aoff[it] + ko);
            cp_commit();
        }
#pragma unroll
        for (int ks = 0; ks < 8; ks++) {
            uint32_t A[4][4], B[2][4];
#pragma unroll
            for (int mt = 0; mt < 4; mt++)
                ldsm4(A[mt], base + aOff + mt * 4096 + ((aK + ks * 32) ^ sw));
#pragma unroll
            for (int p = 0; p < 2; p++)
                ldsm4(B[p], base + OPB + bOff + p * 4096 + ((bK + ks * 32) ^ sw));
#pragma unroll
            for (int mt = 0; mt < 4; mt++)
#pragma unroll
                for (int nt = 0; nt < 4; nt++)
                    mma_tf32(acc[mt][nt], A[mt], B[nt >> 1][(nt & 1) * 2], B[nt >> 1][(nt & 1) * 2 + 1]);
        }
        __syncthreads();
    }

    // ---- epilogue: weighted store to per-slot planes ----
    int g = lane >> 2, t2 = (lane & 3) * 2;
#pragma unroll
    for (int mt = 0; mt < 4; mt++)
#pragma unroll
        for (int nt = 0; nt < 4; nt++) {
            int j = n0 + nw * 32 + nt * 8 + t2;
            int r0 = mw * 64 + mt * 16 + g, r1 = r0 + 8;
            int p0 = s_pair[r0], p1 = s_pair[r1];
            if (p0 >= 0) {
                float wf = g_wt[p0];
                *(float2*)(g_os + (size_t)p0 * HD + j) =
                    make_float2(wf * acc[mt][nt][0], wf * acc[mt][nt][1]);
            }
            if (p1 >= 0) {
                float wf = g_wt[p1];
                *(float2*)(g_os + (size_t)p1 * HD + j) =
                    make_float2(wf * acc[mt][nt][2], wf * acc[mt][nt][3]);
            }
        }
}

// ------------------------- combine ----------------------------------------
__global__ void combine_kernel(float4* __restrict__ out) {
    int i = blockIdx.x * 256 + threadIdx.x;          // over TOK*HD/4
    int t = i >> 8;                                  // 256 float4 per row
    int h4 = i & 255;
    const float4* a = reinterpret_cast<const float4*>(g_os);
    float4 x = a[(size_t)(2 * t) * 256 + h4];
    float4 y = a[(size_t)(2 * t + 1) * 256 + h4];
    out[i] = make_float4(x.x + y.x, x.y + y.y, x.z + y.z, x.w + y.w);
}

// ------------------------- launch -----------------------------------------
extern "C" void kernel_launch(void* const* d_in, const int* in_sizes, int n_in,
                              void* d_out, int out_size) {
    const float* x    = (const float*)d_in[0];
    const float* rl   = (const float*)d_in[1];
    const float* w13  = (const float*)d_in[2];
    const float* w13s = (const float*)d_in[3];
    const float* w2   = (const float*)d_in[4];
    const float* w2s  = (const float*)d_in[5];
    float* out = (float*)d_out;

    const int DSM = 2 * STAGE + 1024;   // 132 KB
    cudaFuncSetAttribute(gemm1_kernel, cudaFuncAttributeMaxDynamicSharedMemorySize, DSM);
    cudaFuncSetAttribute(gemm2_kernel, cudaFuncAttributeMaxDynamicSharedMemorySize, DSM);

    routing_kernel<<<1, TOK>>>(rl);
    convert_x_kernel<<<(TOK * HD) / (256 * 4), 256>>>(x);

    dim3 g1(ID / 64, 8, NE);    // 12 x 8 x 8 (m-tiles beyond Me early-exit)
    gemm1_kernel<<<g1, 256, DSM>>>(w13, w13s);

    dim3 g2(HD / 128, 8, NE);   // 8 x 8 x 8
    gemm2_kernel<<<g2, 256, DSM>>>(w2, w2s);

    combine_kernel<<<(TOK * HD) / (4 * 256), 256>>>(reinterpret_cast<float4*>(out));
}